// round 1
// baseline (speedup 1.0000x reference)
#include <cuda_runtime.h>
#include <math_constants.h>

#define NLAY 5
#define MIX  5
#define MF   50

__device__ float  g_cf[MF];
__device__ float  g_lmw[MF];
__device__ double g_sll;
__device__ double g_slq;

// Deterministic per-launch init: frequency tables + zero accumulators.
__global__ void bnn_init() {
    int i = threadIdx.x;
    if (i == 0) { g_sll = 0.0; g_slq = 0.0; }
    if (i < MF) {
        double e  = -2.0 + 5.0 * (double)i / 49.0;
        double fr = pow(10.0, e);
        double w  = 2.0 * CUDART_PI * fr;
        double MU = 4.0 * CUDART_PI * 1e-7;
        g_cf[i]  = (float)sqrt(w * MU * 0.5);
        g_lmw[i] = (float)log10(MU * w);
    }
}

__device__ __forceinline__ float sigmoidf_(float v) {
    return __fdividef(1.f, 1.f + __expf(-v));
}
__device__ __forceinline__ float softplusf_(float v) {
    return fmaxf(v, 0.f) + __logf(1.f + __expf(-fabsf(v)));
}

__global__ __launch_bounds__(256) void bnn_main(
    const float* __restrict__ x, const float* __restrict__ s,
    const float* __restrict__ ucat, const float* __restrict__ utr, int B)
{
    int b = blockIdx.x * blockDim.x + threadIdx.x;
    float ll_sum = 0.f;
    float lq = 0.f;
    if (b < B) {
        const float* sb = s + (size_t)b * 55;
        const float* xb = x + (size_t)b * 105;

        // ---- mixture weights ----
        float sq[MIX]; float sumsq = 0.f;
        #pragma unroll
        for (int m = 0; m < MIX; m++) { float v = sb[m*11 + 10]; sq[m] = v*v; sumsq += sq[m]; }
        float rinv = __fdividef(1.f, sumsq);

        // ---- categorical component selection ----
        float u = ucat[b];
        float cum = 0.f; int cnt = 0;
        #pragma unroll
        for (int m = 0; m < MIX; m++) { cum += sq[m] * rinv; cnt += (u > cum) ? 1 : 0; }
        int comp = min(cnt, MIX - 1);

        // ---- truncated-normal sampling (selected component) ----
        float q[NLAY];
        const float* sc = sb + comp * 11;
        #pragma unroll
        for (int l = 0; l < NLAY; l++) {
            float lc = 4.f * sigmoidf_(sc[l]);
            float sg = softplusf_(sc[5 + l]);
            float rs = __fdividef(1.f, sg);
            float aa = (0.1f - lc) * rs;
            float bb = (3.9f - lc) * rs;
            float Fa = normcdff(aa);
            float Fb = normcdff(bb);
            float p  = Fa + utr[(size_t)b * NLAY + l] * (Fb - Fa);
            p = fminf(fmaxf(p, 0.f), 1.f);
            float z = normcdfinvf(p);
            q[l] = fminf(fmaxf(fmaf(sg, z, lc), 0.1f), 3.9f);
        }

        // ---- physics precompute: sr = sqrt(res) = 10^(q/2); tq = 2*th/sr ----
        float sr[NLAY], tq[NLAY - 1];
        #pragma unroll
        for (int l = 0; l < NLAY; l++) sr[l] = exp2f(q[l] * 1.66096404744368f);
        #pragma unroll
        for (int j = 0; j < NLAY - 1; j++) tq[j] = 2.f * xb[j] * __fdividef(1.f, sr[j]);

        // ---- frequency loop: 1D MT recursion with Z carried as complex ratio N/D ----
        #pragma unroll 2
        for (int f = 0; f < MF; f++) {
            float cf = g_cf[f];
            float NR = cf * sr[NLAY - 1], NC = NR;   // Z_bottom = cf*sr4*(1+i)
            float DR = 1.f, DC = 0.f;
            #pragma unroll
            for (int j = NLAY - 2; j >= 0; j--) {
                float wj = cf * sr[j];
                float t  = cf * tq[j];
                float t2 = t * t;
                // e^{-(1+i)t}: real = 1 - t + t^3/3 - t^4/6 + t^5/30
                //             imag = -t + t^2 - t^3/3 + t^5/30          (|t| <= 0.112)
                float pr = fmaf(t, 0.03333333333f, -0.16666666667f);
                pr = fmaf(pr, t, 0.33333333333f);
                float ejR = fmaf(pr, t * t2, 1.f - t);
                float pc = fmaf(t2, 0.03333333333f, -0.33333333333f);
                pc = fmaf(pc, t, 1.f);
                float ejC = fmaf(pc, t2, -t);
                // W = wj*(1+i);  WD complex
                float wdr = wj * (DR - DC);
                float wdc = wj * (DR + DC);
                float PR = wdr + NR, PC = wdc + NC;     // W*D + N
                float MR = wdr - NR, MC = wdc - NC;     // W*D - N
                float eMR = ejR * MR - ejC * MC;
                float eMC = ejR * MC + ejC * MR;
                float AR = PR - eMR, AC = PC - eMC;
                DR = PR + eMR; DC = PC + eMC;
                NR = wj * (AR - AC);                    // N' = W*A
                NC = wj * (AR + AC);
            }
            float n2 = NR * NR + NC * NC;
            float d2 = DR * DR + DC * DC;
            float aRes = fmaf(0.30102999566f, __log2f(n2) - __log2f(d2), -g_lmw[f]);
            float ZRu = NR * DR + NC * DC;              // N * conj(D) (unnormalized Z)
            float ZCu = NC * DR - NR * DC;
            float ph = atan2f(ZCu, ZRu);

            // ---- log-likelihood: ll = -0.5*((f-obs)/(0.03|f|))^2 - ln(0.03|f|) - 0.5*ln(2pi)
            float obsA = xb[NLAY + f];
            float obsP = xb[NLAY + MF + f];
            float r1 = __fdividef(aRes - obsA, aRes);
            ll_sum += fmaf(-555.555556f, r1 * r1,
                           fmaf(-0.69314718f, __log2f(fabsf(aRes)), 2.58761937f));
            float r2 = __fdividef(ph - obsP, ph);
            ll_sum += fmaf(-555.555556f, r2 * r2,
                           fmaf(-0.69314718f, __log2f(fabsf(ph)), 2.58761937f));
        }

        // ---- term_q: log q(samples) under full truncated mixture ----
        float clp[MIX];
        #pragma unroll
        for (int m = 0; m < MIX; m++) {
            float acc = __logf(sq[m] * rinv);   // log pro
            const float* sm = sb + m * 11;
            #pragma unroll
            for (int l = 0; l < NLAY; l++) {
                float lc = 4.f * sigmoidf_(sm[l]);
                float sg = softplusf_(sm[5 + l]);
                float rs = __fdividef(1.f, sg);
                float a_ = (0.f - lc) * rs;
                float b_ = (4.f - lc) * rs;
                float dF = normcdff(b_) - normcdff(a_);
                float zc = (q[l] - lc) * rs;
                acc += fmaf(-0.5f, zc * zc, -0.91893853f) - __logf(sg) - __logf(dF);
            }
            clp[m] = acc;
        }
        float mx = clp[0];
        #pragma unroll
        for (int m = 1; m < MIX; m++) mx = fmaxf(mx, clp[m]);
        float se = 0.f;
        #pragma unroll
        for (int m = 0; m < MIX; m++) se += __expf(clp[m] - mx);
        lq = mx + __logf(se);
    }

    // ---- block reduction in double ----
    double v1 = (double)ll_sum, v2 = (double)lq;
    #pragma unroll
    for (int o = 16; o > 0; o >>= 1) {
        v1 += __shfl_down_sync(0xffffffffu, v1, o);
        v2 += __shfl_down_sync(0xffffffffu, v2, o);
    }
    __shared__ double sh1[8], sh2[8];
    int lane = threadIdx.x & 31, wid = threadIdx.x >> 5;
    if (lane == 0) { sh1[wid] = v1; sh2[wid] = v2; }
    __syncthreads();
    if (wid == 0) {
        int nw = blockDim.x >> 5;
        double a = (lane < nw) ? sh1[lane] : 0.0;
        double c = (lane < nw) ? sh2[lane] : 0.0;
        #pragma unroll
        for (int o = 4; o > 0; o >>= 1) {
            a += __shfl_down_sync(0xffffffffu, a, o);
            c += __shfl_down_sync(0xffffffffu, c, o);
        }
        if (lane == 0) { atomicAdd(&g_sll, a); atomicAdd(&g_slq, c); }
    }
}

__global__ void bnn_fin(float* out, int B) {
    double term_lik = -g_sll / ((double)B * (double)(2 * MF));
    double term_q   =  g_slq / (double)B;
    out[0] = (float)(term_lik + term_q + 1.3862943611198906); // + log(4)
}

extern "C" void kernel_launch(void* const* d_in, const int* in_sizes, int n_in,
                              void* d_out, int out_size)
{
    const float* x    = (const float*)d_in[0];
    const float* s    = (const float*)d_in[1];
    const float* ucat = (const float*)d_in[2];
    const float* utr  = (const float*)d_in[3];
    int B = in_sizes[0] / 105;

    bnn_init<<<1, 64>>>();
    int threads = 256;
    int blocks = (B + threads - 1) / threads;
    bnn_main<<<blocks, threads>>>(x, s, ucat, utr, B);
    bnn_fin<<<1, 1>>>((float*)d_out, B);
}

// round 4
// speedup vs baseline: 1.1000x; 1.1000x over previous
#include <cuda_runtime.h>

#define NLAY 5
#define MIX  5
#define MF   50

typedef unsigned long long u64;

__device__ double g_p1[1024];
__device__ double g_p2[1024];
__device__ unsigned int g_cnt = 0;

// ---- f32x2 packed helpers (sm_100+: FFMA2/FMUL2/FADD2) ----
__device__ __forceinline__ u64 PK(float lo, float hi) {
    u64 r; asm("mov.b64 %0,{%1,%2};" : "=l"(r) : "f"(lo), "f"(hi)); return r;
}
__device__ __forceinline__ void UPK(u64 v, float& lo, float& hi) {
    asm("mov.b64 {%0,%1},%2;" : "=f"(lo), "=f"(hi) : "l"(v));
}
__device__ __forceinline__ u64 SP(float x) { return PK(x, x); }
__device__ __forceinline__ u64 F2(u64 a, u64 b, u64 c) {
    u64 r; asm("fma.rn.f32x2 %0,%1,%2,%3;" : "=l"(r) : "l"(a), "l"(b), "l"(c)); return r;
}
__device__ __forceinline__ u64 M2(u64 a, u64 b) {
    u64 r; asm("mul.rn.f32x2 %0,%1,%2;" : "=l"(r) : "l"(a), "l"(b)); return r;
}
__device__ __forceinline__ u64 A2(u64 a, u64 b) {
    u64 r; asm("add.rn.f32x2 %0,%1,%2;" : "=l"(r) : "l"(a), "l"(b)); return r;
}
// negate both lanes: 64-bit sign XOR -> ALU pipe (parallel to FMA pipe)
__device__ __forceinline__ u64 N2(u64 a) { return a ^ 0x8000000080000000ULL; }

__device__ __forceinline__ float sigmoidf_(float v) {
    return __fdividef(1.f, 1.f + __expf(-v));
}
__device__ __forceinline__ float softplusf_(float v) {
    return fmaxf(v, 0.f) + __logf(1.f + __expf(-fabsf(v)));
}

__global__ __launch_bounds__(256) void bnn_all(
    const float* __restrict__ x, const float* __restrict__ s,
    const float* __restrict__ ucat, const float* __restrict__ utr,
    float* __restrict__ out, int B)
{
    // ---- per-block frequency tables ----
    __shared__ float s_cf[MF], s_lmw[MF];
    if (threadIdx.x < MF) {
        int i = threadIdx.x;
        // cf = sqrt(w*MU/2) = 2pi*10^-4.5 * 2^(log2(10)*5i/98)   [verified: cf(0)=1.98692e-4]
        s_cf[i]  = 1.9869176531e-4f * exp2f(0.16948612698f * (float)i);
        // lmw = log10(MU*w) = log10(8*pi^2*1e-7) - 2 + (5/49)i = -7.10254482 + 0.10204i
        s_lmw[i] = -7.1025448154f + 0.1020408163f * (float)i;
    }
    __syncthreads();

    int b = blockIdx.x * blockDim.x + threadIdx.x;
    float ll_sum = 0.f;
    float lq = 0.f;
    if (b < B) {
        const float* sb = s + (size_t)b * 55;
        const float* xb = x + (size_t)b * 105;

        // ---- mixture weights ----
        float sq[MIX]; float sumsq = 0.f;
        #pragma unroll
        for (int m = 0; m < MIX; m++) { float v = sb[m*11 + 10]; sq[m] = v*v; sumsq += sq[m]; }
        float rinv = __fdividef(1.f, sumsq);

        // ---- categorical selection ----
        float u = ucat[b];
        float cum = 0.f; int cnt = 0;
        #pragma unroll
        for (int m = 0; m < MIX; m++) { cum += sq[m] * rinv; cnt += (u > cum) ? 1 : 0; }
        int comp = min(cnt, MIX - 1);

        // ---- truncated-normal sampling (selected component) ----
        float q[NLAY];
        const float* sc = sb + comp * 11;
        #pragma unroll
        for (int l = 0; l < NLAY; l++) {
            float lc = 4.f * sigmoidf_(sc[l]);
            float sg = softplusf_(sc[5 + l]);
            float rs = __fdividef(1.f, sg);
            float aa = (0.1f - lc) * rs;
            float bb = (3.9f - lc) * rs;
            float Fa = normcdff(aa);
            float Fb = normcdff(bb);
            float p  = Fa + utr[(size_t)b * NLAY + l] * (Fb - Fa);
            p = fminf(fmaxf(p, 0.f), 1.f);
            float z = normcdfinvf(p);
            q[l] = fminf(fmaxf(fmaf(sg, z, lc), 0.1f), 3.9f);
        }

        // ---- physics precompute ----
        float sr[NLAY], tq[NLAY - 1];
        #pragma unroll
        for (int l = 0; l < NLAY; l++) sr[l] = exp2f(q[l] * 1.66096404744368f);
        #pragma unroll
        for (int j = 0; j < NLAY - 1; j++) tq[j] = 2.f * xb[j] * __fdividef(1.f, sr[j]);

        // ---- packed constants ----
        const u64 C130 = SP(0.033333335f), Cm16 = SP(-0.16666667f);
        const u64 C13  = SP(0.33333334f),  Cm13 = SP(-0.33333334f);
        const u64 ONE2 = SP(1.0f);
        const u64 A1 = SP(0.9998660f), A3 = SP(-0.3302995f), A5 = SP(0.1801410f);
        const u64 A7 = SP(-0.0851330f), A9 = SP(0.0208351f);
        const u64 C555 = SP(-555.555556f), CLN2 = SP(-0.69314718f);
        const u64 CC = SP(2.58761937f), CL102 = SP(0.30102999566f);

        u64 acc2 = 0ull;

        // ---- frequency loop, 2 freqs per iteration via f32x2 ----
        #pragma unroll 1
        for (int p = 0; p < MF; p += 2) {
            u64 cf2 = PK(s_cf[p], s_cf[p + 1]);
            u64 NRv = M2(cf2, SP(sr[NLAY - 1]));   // Z_bottom = cf*sr4*(1+i), as ratio N/D
            u64 NCv = NRv;
            u64 DRv = ONE2, DCv = 0ull;
            #pragma unroll
            for (int j = NLAY - 2; j >= 0; j--) {
                u64 wj = M2(cf2, SP(sr[j]));
                u64 t  = M2(cf2, SP(tq[j]));
                u64 t2 = M2(t, t);
                u64 nt = N2(t);
                // e^{-(1+i)t}, |t| <= 0.112: degree-5 Taylor
                u64 pr = F2(t, C130, Cm16);  pr = F2(pr, t, C13);
                u64 t3 = M2(t, t2);
                u64 omt = A2(ONE2, nt);
                u64 ejR = F2(pr, t3, omt);
                u64 pc = F2(t2, C130, Cm13); pc = F2(pc, t, ONE2);
                u64 ejC = F2(pc, t2, nt);
                // W = wj*(1+i)
                u64 wdr = M2(wj, A2(DRv, N2(DCv)));
                u64 wdc = M2(wj, A2(DRv, DCv));
                u64 PRv = A2(wdr, NRv), PCv = A2(wdc, NCv);
                u64 MRv = A2(wdr, N2(NRv)), MCv = A2(wdc, N2(NCv));
                u64 eMR = F2(ejR, MRv, N2(M2(ejC, MCv)));
                u64 eMC = F2(ejR, MCv, M2(ejC, MRv));
                u64 ARv = A2(PRv, N2(eMR)), ACv = A2(PCv, N2(eMC));
                DRv = A2(PRv, eMR); DCv = A2(PCv, eMC);
                NRv = M2(wj, A2(ARv, N2(ACv)));
                NCv = M2(wj, A2(ARv, ACv));
            }
            u64 n2v = F2(NRv, NRv, M2(NCv, NCv));
            u64 d2v = F2(DRv, DRv, M2(DCv, DCv));
            u64 ZRv = F2(NCv, DCv, M2(NRv, DRv));   // N*conj(D): unnormalized Z
            u64 ZCv = F2(NCv, DRv, N2(M2(NRv, DCv)));
            float n2a, n2b, d2a, d2b, zra, zrb, zca, zcb;
            UPK(n2v, n2a, n2b); UPK(d2v, d2a, d2b);
            UPK(ZRv, zra, zrb); UPK(ZCv, zca, zcb);

            // aRes = log10(|N|^2/|D|^2) - log10(mu*w)
            u64 lgv = PK(__log2f(n2a) - __log2f(d2a), __log2f(n2b) - __log2f(d2b));
            u64 aResV = F2(CL102, lgv, PK(-s_lmw[p], -s_lmw[p + 1]));
            float aA, aB; UPK(aResV, aA, aB);

            // phase: first quadrant -> min/max ratio + packed deg-9 poly
            float r0 = __fdividef(fminf(zca, zra), fmaxf(zca, zra));
            float r1 = __fdividef(fminf(zcb, zrb), fmaxf(zcb, zrb));
            u64 rv = PK(r0, r1);
            u64 sv = M2(rv, rv);
            u64 pp = F2(sv, A9, A7); pp = F2(pp, sv, A5);
            pp = F2(pp, sv, A3);     pp = F2(pp, sv, A1);
            u64 av = M2(pp, rv);
            float at0, at1; UPK(av, at0, at1);
            float ph0 = (zca > zra) ? (1.57079632679f - at0) : at0;
            float ph1 = (zcb > zrb) ? (1.57079632679f - at1) : at1;

            // log-likelihood (amplitude + phase), packed accumulate
            float ra0 = __fdividef(aA - xb[NLAY + p],     aA);
            float ra1 = __fdividef(aB - xb[NLAY + p + 1], aB);
            u64 rAv = PK(ra0, ra1);
            u64 lgA = PK(__log2f(fabsf(aA)), __log2f(fabsf(aB)));
            acc2 = A2(acc2, F2(C555, M2(rAv, rAv), F2(CLN2, lgA, CC)));

            float rp0 = __fdividef(ph0 - xb[NLAY + MF + p],     ph0);
            float rp1 = __fdividef(ph1 - xb[NLAY + MF + p + 1], ph1);
            u64 rPv = PK(rp0, rp1);
            u64 lgP = PK(__log2f(ph0), __log2f(ph1));
            acc2 = A2(acc2, F2(C555, M2(rPv, rPv), F2(CLN2, lgP, CC)));
        }
        { float la, lb_; UPK(acc2, la, lb_); ll_sum = la + lb_; }

        // ---- term_q: log q(samples) under full truncated mixture ----
        float clp[MIX];
        #pragma unroll
        for (int m = 0; m < MIX; m++) {
            float acc = __logf(sq[m] * rinv);
            const float* sm = sb + m * 11;
            #pragma unroll
            for (int l = 0; l < NLAY; l++) {
                float lc = 4.f * sigmoidf_(sm[l]);
                float sg = softplusf_(sm[5 + l]);
                float rs = __fdividef(1.f, sg);
                float a_ = (0.f - lc) * rs;
                float b_ = (4.f - lc) * rs;
                float dF = normcdff(b_) - normcdff(a_);
                float zc = (q[l] - lc) * rs;
                acc += fmaf(-0.5f, zc * zc, -0.91893853f) - __logf(sg) - __logf(dF);
            }
            clp[m] = acc;
        }
        float mx = clp[0];
        #pragma unroll
        for (int m = 1; m < MIX; m++) mx = fmaxf(mx, clp[m]);
        float se = 0.f;
        #pragma unroll
        for (int m = 0; m < MIX; m++) se += __expf(clp[m] - mx);
        lq = mx + __logf(se);
    }

    // ---- block reduction (double) ----
    double v1 = (double)ll_sum, v2 = (double)lq;
    #pragma unroll
    for (int o = 16; o > 0; o >>= 1) {
        v1 += __shfl_down_sync(0xffffffffu, v1, o);
        v2 += __shfl_down_sync(0xffffffffu, v2, o);
    }
    __shared__ double sh1[8], sh2[8];
    __shared__ bool amLast;
    int lane = threadIdx.x & 31, wid = threadIdx.x >> 5;
    if (lane == 0) { sh1[wid] = v1; sh2[wid] = v2; }
    __syncthreads();
    if (wid == 0) {
        int nw = blockDim.x >> 5;
        double a = (lane < nw) ? sh1[lane] : 0.0;
        double c = (lane < nw) ? sh2[lane] : 0.0;
        #pragma unroll
        for (int o = 4; o > 0; o >>= 1) {
            a += __shfl_down_sync(0xffffffffu, a, o);
            c += __shfl_down_sync(0xffffffffu, c, o);
        }
        if (lane == 0) {
            g_p1[blockIdx.x] = a;
            g_p2[blockIdx.x] = c;
            __threadfence();
            unsigned int t = atomicAdd(&g_cnt, 1u);
            amLast = (t == gridDim.x - 1);
        }
    }
    __syncthreads();

    // ---- last block: final reduction + output ----
    if (amLast) {
        __threadfence();
        double s1 = 0.0, s2 = 0.0;
        for (int i = threadIdx.x; i < (int)gridDim.x; i += blockDim.x) {
            s1 += __ldcg(&g_p1[i]);
            s2 += __ldcg(&g_p2[i]);
        }
        #pragma unroll
        for (int o = 16; o > 0; o >>= 1) {
            s1 += __shfl_down_sync(0xffffffffu, s1, o);
            s2 += __shfl_down_sync(0xffffffffu, s2, o);
        }
        __syncthreads();   // reuse sh1/sh2
        if (lane == 0) { sh1[wid] = s1; sh2[wid] = s2; }
        __syncthreads();
        if (wid == 0) {
            int nw = blockDim.x >> 5;
            double a = (lane < nw) ? sh1[lane] : 0.0;
            double c = (lane < nw) ? sh2[lane] : 0.0;
            #pragma unroll
            for (int o = 4; o > 0; o >>= 1) {
                a += __shfl_down_sync(0xffffffffu, a, o);
                c += __shfl_down_sync(0xffffffffu, c, o);
            }
            if (lane == 0) {
                double term_lik = -a / ((double)B * (double)(2 * MF));
                double term_q   =  c / (double)B;
                out[0] = (float)(term_lik + term_q + 1.3862943611198906); // + log(4)
                g_cnt = 0;  // reset for next replay (deterministic)
            }
        }
    }
}

extern "C" void kernel_launch(void* const* d_in, const int* in_sizes, int n_in,
                              void* d_out, int out_size)
{
    const float* x    = (const float*)d_in[0];
    const float* s    = (const float*)d_in[1];
    const float* ucat = (const float*)d_in[2];
    const float* utr  = (const float*)d_in[3];
    int B = in_sizes[0] / 105;

    int threads = 256;
    int blocks = (B + threads - 1) / threads;   // 512 for B=131072
    bnn_all<<<blocks, threads>>>(x, s, ucat, utr, (float*)d_out, B);
}

// round 5
// speedup vs baseline: 1.3591x; 1.2355x over previous
#include <cuda_runtime.h>

#define NLAY 5
#define MIX  5
#define MF   50

typedef unsigned long long u64;

__device__ double g_p1[1024];
__device__ double g_p2[1024];
__device__ unsigned int g_cnt = 0;

// ---- f32x2 packed helpers (sm_100+: FFMA2/FMUL2/FADD2) ----
__device__ __forceinline__ u64 PK(float lo, float hi) {
    u64 r; asm("mov.b64 %0,{%1,%2};" : "=l"(r) : "f"(lo), "f"(hi)); return r;
}
__device__ __forceinline__ void UPK(u64 v, float& lo, float& hi) {
    asm("mov.b64 {%0,%1},%2;" : "=f"(lo), "=f"(hi) : "l"(v));
}
__device__ __forceinline__ u64 SP(float x) { return PK(x, x); }
__device__ __forceinline__ u64 F2(u64 a, u64 b, u64 c) {
    u64 r; asm("fma.rn.f32x2 %0,%1,%2,%3;" : "=l"(r) : "l"(a), "l"(b), "l"(c)); return r;
}
__device__ __forceinline__ u64 M2(u64 a, u64 b) {
    u64 r; asm("mul.rn.f32x2 %0,%1,%2;" : "=l"(r) : "l"(a), "l"(b)); return r;
}
__device__ __forceinline__ u64 A2(u64 a, u64 b) {
    u64 r; asm("add.rn.f32x2 %0,%1,%2;" : "=l"(r) : "l"(a), "l"(b)); return r;
}
// negate both lanes: 64-bit sign XOR -> ALU pipe (parallel to FMA pipe)
__device__ __forceinline__ u64 N2(u64 a) { return a ^ 0x8000000080000000ULL; }

__device__ __forceinline__ float sigmoidf_(float v) {
    return __fdividef(1.f, 1.f + __expf(-v));
}
__device__ __forceinline__ float softplusf_(float v) {
    return fmaxf(v, 0.f) + __logf(1.f + __expf(-fabsf(v)));
}
// Abramowitz-Stegun 26.2.17 normal CDF, |abs err| < 7.5e-8, ~12 instrs
__device__ __forceinline__ float ndtr_(float x) {
    float ax = fabsf(x);
    float t = __fdividef(1.f, fmaf(0.2316419f, ax, 1.f));
    float poly = t * fmaf(t, fmaf(t, fmaf(t, fmaf(t, 1.330274429f, -1.821255978f),
                         1.781477937f), -0.356563782f), 0.319381530f);
    float c = 0.39894228040f * __expf(-0.5f * ax * ax) * poly;  // upper tail of |x|
    return (x >= 0.f) ? 1.f - c : c;
}

__global__ __launch_bounds__(256) void bnn_all(
    const float* __restrict__ x, const float* __restrict__ s,
    const float* __restrict__ ucat, const float* __restrict__ utr,
    float* __restrict__ out, int B)
{
    // ---- per-block frequency tables ----
    __shared__ float s_cf[MF], s_lmw[MF];
    if (threadIdx.x < MF) {
        int i = threadIdx.x;
        // cf = sqrt(w*MU/2) = 2pi*10^-4.5 * 2^(log2(10)*5i/98)
        s_cf[i]  = 1.9869176531e-4f * exp2f(0.16948612698f * (float)i);
        // lmw = log10(MU*w) = log10(8*pi^2*1e-7) - 2 + (5/49)i
        s_lmw[i] = -7.1025448154f + 0.1020408163f * (float)i;
    }
    __syncthreads();

    int b = blockIdx.x * blockDim.x + threadIdx.x;
    float ll_sum = 0.f;
    float lq = 0.f;
    if (b < B) {
        const float* sb = s + (size_t)b * 55;
        const float* xb = x + (size_t)b * 105;

        // ---- mixture weights ----
        float sq[MIX]; float sumsq = 0.f;
        #pragma unroll
        for (int m = 0; m < MIX; m++) { float v = sb[m*11 + 10]; sq[m] = v*v; sumsq += sq[m]; }
        float rinv = __fdividef(1.f, sumsq);

        // ---- categorical selection ----
        float u = ucat[b];
        float cum = 0.f; int cnt = 0;
        #pragma unroll
        for (int m = 0; m < MIX; m++) { cum += sq[m] * rinv; cnt += (u > cum) ? 1 : 0; }
        int comp = min(cnt, MIX - 1);

        // ---- truncated-normal sampling (selected component) ----
        float q[NLAY];
        const float* sc = sb + comp * 11;
        #pragma unroll
        for (int l = 0; l < NLAY; l++) {
            float lc = 4.f * sigmoidf_(sc[l]);
            float sg = softplusf_(sc[5 + l]);
            float rs = __fdividef(1.f, sg);
            float aa = (0.1f - lc) * rs;
            float bb = (3.9f - lc) * rs;
            float Fa = ndtr_(aa);
            float Fb = ndtr_(bb);
            float p  = Fa + utr[(size_t)b * NLAY + l] * (Fb - Fa);
            p = fminf(fmaxf(p, 0.f), 1.f);
            float z = normcdfinvf(p);
            q[l] = fminf(fmaxf(fmaf(sg, z, lc), 0.1f), 3.9f);
        }

        // ---- physics precompute ----
        float sr[NLAY], tq[NLAY - 1];
        #pragma unroll
        for (int l = 0; l < NLAY; l++) sr[l] = exp2f(q[l] * 1.66096404744368f);
        #pragma unroll
        for (int j = 0; j < NLAY - 1; j++) tq[j] = 2.f * xb[j] * __fdividef(1.f, sr[j]);

        // ---- packed constants ----
        const u64 C130 = SP(0.033333335f), Cm16 = SP(-0.16666667f);
        const u64 C13  = SP(0.33333334f),  Cm13 = SP(-0.33333334f);
        const u64 ONE2 = SP(1.0f);
        // degree-15 minimax atan on [-1,1], max err ~1e-7
        const u64 A1  = SP(0.9999993329f),  A3  = SP(-0.3332985605f);
        const u64 A5  = SP(0.1994653599f),  A7  = SP(-0.1390853351f);
        const u64 A9  = SP(0.0964200441f),  A11 = SP(-0.0559098861f);
        const u64 A13 = SP(0.0218612288f),  A15 = SP(-0.0040540580f);
        const u64 C555 = SP(-555.555556f), CLN2 = SP(-0.69314718f);
        const u64 CC = SP(2.58761937f), CL102 = SP(0.30102999566f);

        u64 acc2 = 0ull;

        // ---- frequency loop, 2 freqs/iter via f32x2; unroll 2 pairs for ILP ----
        #pragma unroll 2
        for (int p = 0; p < MF; p += 2) {
            u64 cf2 = PK(s_cf[p], s_cf[p + 1]);
            u64 NRv = M2(cf2, SP(sr[NLAY - 1]));   // Z_bottom = cf*sr4*(1+i), as ratio N/D
            u64 NCv = NRv;
            u64 DRv = ONE2, DCv = 0ull;
            #pragma unroll
            for (int j = NLAY - 2; j >= 0; j--) {
                u64 wj = M2(cf2, SP(sr[j]));
                u64 t  = M2(cf2, SP(tq[j]));
                u64 t2 = M2(t, t);
                u64 nt = N2(t);
                // e^{-(1+i)t}, |t| <= 0.112: degree-5 Taylor
                u64 pr = F2(t, C130, Cm16);  pr = F2(pr, t, C13);
                u64 t3 = M2(t, t2);
                u64 omt = A2(ONE2, nt);
                u64 ejR = F2(pr, t3, omt);
                u64 pc = F2(t2, C130, Cm13); pc = F2(pc, t, ONE2);
                u64 ejC = F2(pc, t2, nt);
                // W = wj*(1+i)
                u64 wdr = M2(wj, A2(DRv, N2(DCv)));
                u64 wdc = M2(wj, A2(DRv, DCv));
                u64 PRv = A2(wdr, NRv), PCv = A2(wdc, NCv);
                u64 MRv = A2(wdr, N2(NRv)), MCv = A2(wdc, N2(NCv));
                u64 eMR = F2(ejR, MRv, N2(M2(ejC, MCv)));
                u64 eMC = F2(ejR, MCv, M2(ejC, MRv));
                u64 ARv = A2(PRv, N2(eMR)), ACv = A2(PCv, N2(eMC));
                DRv = A2(PRv, eMR); DCv = A2(PCv, eMC);
                NRv = M2(wj, A2(ARv, N2(ACv)));
                NCv = M2(wj, A2(ARv, ACv));
            }
            u64 n2v = F2(NRv, NRv, M2(NCv, NCv));
            u64 d2v = F2(DRv, DRv, M2(DCv, DCv));
            u64 ZRv = F2(NCv, DCv, M2(NRv, DRv));   // N*conj(D): unnormalized Z
            u64 ZCv = F2(NCv, DRv, N2(M2(NRv, DCv)));
            float n2a, n2b, d2a, d2b, zra, zrb, zca, zcb;
            UPK(n2v, n2a, n2b); UPK(d2v, d2a, d2b);
            UPK(ZRv, zra, zrb); UPK(ZCv, zca, zcb);

            // aRes = log10(|N|^2/|D|^2) - log10(mu*w)
            u64 lgv = PK(__log2f(n2a) - __log2f(d2a), __log2f(n2b) - __log2f(d2b));
            u64 aResV = F2(CL102, lgv, PK(-s_lmw[p], -s_lmw[p + 1]));
            float aA, aB; UPK(aResV, aA, aB);

            // phase: first quadrant -> min/max ratio + packed deg-15 poly
            float r0 = __fdividef(fminf(zca, zra), fmaxf(zca, zra));
            float r1 = __fdividef(fminf(zcb, zrb), fmaxf(zcb, zrb));
            u64 rv = PK(r0, r1);
            u64 sv = M2(rv, rv);
            u64 pp = F2(sv, A15, A13); pp = F2(pp, sv, A11);
            pp = F2(pp, sv, A9);       pp = F2(pp, sv, A7);
            pp = F2(pp, sv, A5);       pp = F2(pp, sv, A3);
            pp = F2(pp, sv, A1);
            u64 av = M2(pp, rv);
            float at0, at1; UPK(av, at0, at1);
            float ph0 = (zca > zra) ? (1.57079632679f - at0) : at0;
            float ph1 = (zcb > zrb) ? (1.57079632679f - at1) : at1;

            // log-likelihood (amplitude + phase), packed accumulate
            float ra0 = __fdividef(aA - xb[NLAY + p],     aA);
            float ra1 = __fdividef(aB - xb[NLAY + p + 1], aB);
            u64 rAv = PK(ra0, ra1);
            u64 lgA = PK(__log2f(fabsf(aA)), __log2f(fabsf(aB)));
            acc2 = A2(acc2, F2(C555, M2(rAv, rAv), F2(CLN2, lgA, CC)));

            float rp0 = __fdividef(ph0 - xb[NLAY + MF + p],     ph0);
            float rp1 = __fdividef(ph1 - xb[NLAY + MF + p + 1], ph1);
            u64 rPv = PK(rp0, rp1);
            u64 lgP = PK(__log2f(ph0), __log2f(ph1));
            acc2 = A2(acc2, F2(C555, M2(rPv, rPv), F2(CLN2, lgP, CC)));
        }
        { float la, lb_; UPK(acc2, la, lb_); ll_sum = la + lb_; }

        // ---- term_q: log q(samples) under full truncated mixture ----
        float clp[MIX];
        #pragma unroll
        for (int m = 0; m < MIX; m++) {
            float acc = __logf(sq[m] * rinv);
            const float* sm = sb + m * 11;
            #pragma unroll
            for (int l = 0; l < NLAY; l++) {
                float lc = 4.f * sigmoidf_(sm[l]);
                float sg = softplusf_(sm[5 + l]);
                float rs = __fdividef(1.f, sg);
                float a_ = (0.f - lc) * rs;
                float b_ = (4.f - lc) * rs;
                float dF = ndtr_(b_) - ndtr_(a_);
                float zc = (q[l] - lc) * rs;
                acc += fmaf(-0.5f, zc * zc, -0.91893853f) - __logf(sg) - __logf(dF);
            }
            clp[m] = acc;
        }
        float mx = clp[0];
        #pragma unroll
        for (int m = 1; m < MIX; m++) mx = fmaxf(mx, clp[m]);
        float se = 0.f;
        #pragma unroll
        for (int m = 0; m < MIX; m++) se += __expf(clp[m] - mx);
        lq = mx + __logf(se);
    }

    // ---- block reduction (double) ----
    double v1 = (double)ll_sum, v2 = (double)lq;
    #pragma unroll
    for (int o = 16; o > 0; o >>= 1) {
        v1 += __shfl_down_sync(0xffffffffu, v1, o);
        v2 += __shfl_down_sync(0xffffffffu, v2, o);
    }
    __shared__ double sh1[8], sh2[8];
    __shared__ bool amLast;
    int lane = threadIdx.x & 31, wid = threadIdx.x >> 5;
    if (lane == 0) { sh1[wid] = v1; sh2[wid] = v2; }
    __syncthreads();
    if (wid == 0) {
        int nw = blockDim.x >> 5;
        double a = (lane < nw) ? sh1[lane] : 0.0;
        double c = (lane < nw) ? sh2[lane] : 0.0;
        #pragma unroll
        for (int o = 4; o > 0; o >>= 1) {
            a += __shfl_down_sync(0xffffffffu, a, o);
            c += __shfl_down_sync(0xffffffffu, c, o);
        }
        if (lane == 0) {
            g_p1[blockIdx.x] = a;
            g_p2[blockIdx.x] = c;
            __threadfence();
            unsigned int t = atomicAdd(&g_cnt, 1u);
            amLast = (t == gridDim.x - 1);
        }
    }
    __syncthreads();

    // ---- last block: final reduction + output ----
    if (amLast) {
        __threadfence();
        double s1 = 0.0, s2 = 0.0;
        for (int i = threadIdx.x; i < (int)gridDim.x; i += blockDim.x) {
            s1 += __ldcg(&g_p1[i]);
            s2 += __ldcg(&g_p2[i]);
        }
        #pragma unroll
        for (int o = 16; o > 0; o >>= 1) {
            s1 += __shfl_down_sync(0xffffffffu, s1, o);
            s2 += __shfl_down_sync(0xffffffffu, s2, o);
        }
        __syncthreads();   // reuse sh1/sh2
        if (lane == 0) { sh1[wid] = s1; sh2[wid] = s2; }
        __syncthreads();
        if (wid == 0) {
            int nw = blockDim.x >> 5;
            double a = (lane < nw) ? sh1[lane] : 0.0;
            double c = (lane < nw) ? sh2[lane] : 0.0;
            #pragma unroll
            for (int o = 4; o > 0; o >>= 1) {
                a += __shfl_down_sync(0xffffffffu, a, o);
                c += __shfl_down_sync(0xffffffffu, c, o);
            }
            if (lane == 0) {
                double term_lik = -a / ((double)B * (double)(2 * MF));
                double term_q   =  c / (double)B;
                out[0] = (float)(term_lik + term_q + 1.3862943611198906); // + log(4)
                g_cnt = 0;  // reset for next replay (deterministic)
            }
        }
    }
}

extern "C" void kernel_launch(void* const* d_in, const int* in_sizes, int n_in,
                              void* d_out, int out_size)
{
    const float* x    = (const float*)d_in[0];
    const float* s    = (const float*)d_in[1];
    const float* ucat = (const float*)d_in[2];
    const float* utr  = (const float*)d_in[3];
    int B = in_sizes[0] / 105;

    int threads = 256;
    int blocks = (B + threads - 1) / threads;   // 512 for B=131072
    bnn_all<<<blocks, threads>>>(x, s, ucat, utr, (float*)d_out, B);
}